// round 15
// baseline (speedup 1.0000x reference)
#include <cuda_runtime.h>
#include <cuda_fp16.h>
#include <math.h>
#include <stdint.h>

#define N 4096
#define D 512
#define NT 32
#define SYM_TILES 1056                    // sum_{I=0}^{31} (64 - 2I)
#define GRID_TILES (SYM_TILES * 2 + 2048) // 4160

// ---------------- device scratch ----------------
__device__ __half g_h1[N * D];
__device__ __half g_h2[N * D];
__device__ unsigned g_bits[6][N][128];   // bit-packed adjacency (12.6 MB)

// Accumulator layout (row-indexed, length N each):
//  0..2 sI1, 3..5 sX12, 6..8 sI2, 9..11 sX21,
//  12..16 wI1, 17..21 wX12, 22..26 wI2, 27..31 wX21,
//  32..34 rA, 35..37 rG, 40 d12 (38,39 unused)
#define ACC_TOTAL (41 * N)
__device__ float g_acc[ACC_TOTAL];
__device__ float g_tot[13];

// smem: 3 buffers x (A 16KB + B 8KB) = 73728. Post-MMA C[128][72] (36864 B)
// reuses buf0 + low buf1; rotated mapping puts the last chunk in buf2 (no race).
// sAcc (2 x 4KB) at 73728, colAcc (192 floats) at 81920.
#define BUF_STRIDE 24576
#define SACC_OFF 73728
#define COLACC_OFF 81920
#define SMEM_BYTES (81920 + 768)
#define CSTRIDE 72

#define SWZ(o) ((o) ^ (((o) >> 3) & 0x70))

// ---------------- PTX helpers ----------------
__device__ __forceinline__ uint32_t smem_u32_of(const void* p) {
    uint32_t a;
    asm("{ .reg .u64 t; cvta.to.shared.u64 t, %1; cvt.u32.u64 %0, t; }" : "=r"(a) : "l"(p));
    return a;
}
__device__ __forceinline__ void ldsm4(uint32_t* r, uint32_t addr) {
    asm volatile("ldmatrix.sync.aligned.m8n8.x4.shared.b16 {%0,%1,%2,%3}, [%4];"
                 : "=r"(r[0]), "=r"(r[1]), "=r"(r[2]), "=r"(r[3]) : "r"(addr));
}
__device__ __forceinline__ void mma16816(float* c, const uint32_t* a, const uint32_t* b) {
    asm volatile(
        "mma.sync.aligned.m16n8k16.row.col.f32.f16.f16.f32 "
        "{%0,%1,%2,%3}, {%4,%5,%6,%7}, {%8,%9}, {%0,%1,%2,%3};"
        : "+f"(c[0]), "+f"(c[1]), "+f"(c[2]), "+f"(c[3])
        : "r"(a[0]), "r"(a[1]), "r"(a[2]), "r"(a[3]), "r"(b[0]), "r"(b[1]));
}
__device__ __forceinline__ void cp16(uint32_t dst, const void* src) {
    asm volatile("cp.async.cg.shared.global [%0], [%1], 16;" :: "r"(dst), "l"(src));
}
#define CP_COMMIT() asm volatile("cp.async.commit_group;" ::: "memory")

// ---------------- small kernels ----------------
__global__ void zero_acc_kernel() {
    int i = blockIdx.x * blockDim.x + threadIdx.x;
    if (i < ACC_TOTAL) g_acc[i] = 0.0f;
    if (i < 13) g_tot[i] = 0.0f;
}

// Bit-pack adjacency + row sums. grid(N, 6), block 128, float4 loads.
__global__ void pack_adj_kernel(const float* __restrict__ a0, const float* __restrict__ a1,
                                const float* __restrict__ a2, const float* __restrict__ a3,
                                const float* __restrict__ a4, const float* __restrict__ a5) {
    const int row = blockIdx.x, mat = blockIdx.y, t = threadIdx.x;
    const float* src;
    switch (mat) {
        case 0: src = a0; break; case 1: src = a1; break; case 2: src = a2; break;
        case 3: src = a3; break; case 4: src = a4; break; default: src = a5; break;
    }
    const int lane = t & 31, w = t >> 5;
    int cnt = 0;
#pragma unroll
    for (int it = 0; it < 8; it++) {
        float4 v = *(const float4*)(src + (size_t)row * N + it * 512 + t * 4);
        unsigned nib = (unsigned)(v.x != 0.0f) | ((unsigned)(v.y != 0.0f) << 1) |
                       ((unsigned)(v.z != 0.0f) << 2) | ((unsigned)(v.w != 0.0f) << 3);
        cnt += __popc(nib);
        unsigned val = nib << (4 * (t & 7));
        val |= __shfl_xor_sync(0xffffffffu, val, 1);
        val |= __shfl_xor_sync(0xffffffffu, val, 2);
        val |= __shfl_xor_sync(0xffffffffu, val, 4);
        if ((t & 7) == 0) g_bits[mat][row][it * 16 + (t >> 3)] = val;
    }
#pragma unroll
    for (int o = 16; o; o >>= 1) cnt += __shfl_xor_sync(0xffffffffu, cnt, o);
    __shared__ int sc[4];
    if (lane == 0) sc[w] = cnt;
    __syncthreads();
    if (t == 0)
        g_acc[(32 + mat) * N + row] = (float)(sc[0] + sc[1] + sc[2] + sc[3]);
}

// Normalize fp32 -> fp16. grid(N,2), block 128.
__global__ void normalize_kernel(const float* __restrict__ z1,
                                 const float* __restrict__ z2) {
    int row = blockIdx.x;
    const float* src = (blockIdx.y == 0) ? z1 : z2;
    __half* dst = (blockIdx.y == 0) ? g_h1 : g_h2;
    int t = threadIdx.x;

    float4 v = ((const float4*)(src + (size_t)row * D))[t];
    float s = v.x * v.x + v.y * v.y + v.z * v.z + v.w * v.w;
#pragma unroll
    for (int o = 16; o; o >>= 1) s += __shfl_xor_sync(0xffffffffu, s, o);
    __shared__ float ws[4];
    if ((t & 31) == 0) ws[t >> 5] = s;
    __syncthreads();
    float inv = 1.0f / fmaxf(sqrtf(ws[0] + ws[1] + ws[2] + ws[3]), 1e-12f);
    size_t base = (size_t)row * D + t * 4;
    dst[base + 0] = __float2half_rn(v.x * inv);
    dst[base + 1] = __float2half_rn(v.y * inv);
    dst[base + 2] = __float2half_rn(v.z * inv);
    dst[base + 3] = __float2half_rn(v.w * inv);
}

// diag(S12): fp32 dot of normalized fp16 rows. grid N, block 128.
__global__ void diag12_kernel() {
    const int row = blockIdx.x, t = threadIdx.x;
    const __half2* a = (const __half2*)(g_h1 + (size_t)row * D);
    const __half2* b = (const __half2*)(g_h2 + (size_t)row * D);
    float s = 0.0f;
#pragma unroll
    for (int k = 0; k < 2; k++) {
        float2 fa = __half22float2(a[t + k * 128]);
        float2 fb = __half22float2(b[t + k * 128]);
        s += fa.x * fb.x + fa.y * fb.y;
    }
#pragma unroll
    for (int o = 16; o; o >>= 1) s += __shfl_xor_sync(0xffffffffu, s, o);
    __shared__ float ws[4];
    if ((t & 31) == 0) ws[t >> 5] = s;
    __syncthreads();
    if (t == 0) g_acc[40 * N + row] = ws[0] + ws[1] + ws[2] + ws[3];
}

// ---------------- gram kernel ----------------
// 1D grid over 4160 tiles of 128 rows x 64 cols. 256 thr, 8 warps (4x2),
// warp tile 32x32. Dense row+col sums fused in one register sweep;
// masked stats via union-bitmask + ffs over the smem C dump.
__global__ void __launch_bounds__(256, 2) gram_kernel() {
    extern __shared__ char smem[];
    float* Cs = (float*)smem;                      // post-MMA reuse, [128][72]
    float* sAcc = (float*)(smem + SACC_OFF);       // [2][128][8]
    float* colAcc = (float*)(smem + COLACC_OFF);   // [64][3]
    const uint32_t sb = smem_u32_of(smem);
    const int tid = threadIdx.x, lane = tid & 31, wid = tid >> 5;
    const int wm = wid & 3, wn = wid >> 2;

    // ---- decode (pass, I, Jh) ----
    int pass, I, Jh;
    {
        int t = blockIdx.x;
        if (t < 2 * SYM_TILES) {
            pass = (t < SYM_TILES) ? 0 : 1;
            int rem = t - pass * SYM_TILES;
            int i = 0;
            while (rem >= 64 - 2 * i) { rem -= 64 - 2 * i; i++; }
            I = i; Jh = 2 * i + rem;
        } else {
            pass = 2;
            int u = t - 2 * SYM_TILES;
            I = u >> 6; Jh = u & 63;
        }
    }
    const bool doCol = (pass == 2) || (Jh >= 2 * I + 2);
    const bool adjTypeR = (pass != 1);
    const bool adjTypeC = (pass == 0);
    const int mbR = adjTypeR ? 0 : 3;
    const int mbC = adjTypeC ? 0 : 3;

    // ---- hoisted sparse-mask words ----
    const int rsRow = I * 128 + (tid >> 1);
    const int rsWord = Jh * 2 + (tid & 1);
    unsigned rw0 = g_bits[mbR + 0][rsRow][rsWord];
    unsigned rw1 = g_bits[mbR + 1][rsRow][rsWord];
    unsigned rw2 = g_bits[mbR + 2][rsRow][rsWord];
    const int csCol = Jh * 64 + (tid >> 2);
    unsigned cw0 = 0, cw1 = 0, cw2 = 0;
    if (doCol) {
        cw0 = g_bits[mbC + 0][csCol][I * 4 + (tid & 3)];
        cw1 = g_bits[mbC + 1][csCol][I * 4 + (tid & 3)];
        cw2 = g_bits[mbC + 2][csCol][I * 4 + (tid & 3)];
    }

    // zero colAcc (covered by the loop's first __syncthreads)
    if (tid < 192) colAcc[tid] = 0.0f;

    // ldmatrix lane addressing
    const int arow = wm * 32 + (lane & 15);
    const uint32_t akb0 = (uint32_t)((lane >> 4) * 16);
    const int brow = wn * 32 + ((lane >> 4) * 8) + (lane & 7);
    const uint32_t bkb0 = (uint32_t)(((lane >> 3) & 1) * 16);
    uint32_t aRT[2], aXV[2], bRT[2], bXV[2];
#pragma unroll
    for (int mt = 0; mt < 2; mt++) {
        int r = arow + mt * 16;
        aRT[mt] = (uint32_t)(r * 128);
        aXV[mt] = (uint32_t)((r & 7) << 4);
    }
#pragma unroll
    for (int j = 0; j < 2; j++) {
        int r = brow + j * 16;
        bRT[j] = (uint32_t)(16384 + r * 128);
        bXV[j] = (uint32_t)((r & 7) << 4);
    }

    // staging decomposition: A = 1024 16B units (4/thread), B = 512 (2/thread)
    const int sRow[4] = {(tid + 0) >> 3, (tid + 256) >> 3, (tid + 512) >> 3, (tid + 768) >> 3};
    const int sSeg[4] = {(tid + 0) & 7, (tid + 256) & 7, (tid + 512) & 7, (tid + 768) & 7};
    uint32_t dA[4], dB[2];
#pragma unroll
    for (int i = 0; i < 4; i++) dA[i] = SWZ((uint32_t)(sRow[i] * 128 + sSeg[i] * 16));
#pragma unroll
    for (int i = 0; i < 2; i++)
        dB[i] = 16384u + SWZ((uint32_t)((sRow[i] & 63) * 128 + sSeg[i] * 16));

    const __half* Ap = (pass == 1) ? g_h2 : g_h1;
    const __half* Bp = (pass == 0) ? g_h1 : g_h2;
    const __half* Ag = Ap + (size_t)I * 128 * D;
    const __half* Bg = Bp + (size_t)Jh * 64 * D;
    const __half* srcA[4];
    const __half* srcB[2];
#pragma unroll
    for (int i = 0; i < 4; i++) srcA[i] = Ag + (size_t)sRow[i] * D + sSeg[i] * 8;
#pragma unroll
    for (int i = 0; i < 2; i++) srcB[i] = Bg + (size_t)(sRow[i] & 63) * D + sSeg[i] * 8;

    float cfr[8][4];
#pragma unroll
    for (int i = 0; i < 8; i++)
#pragma unroll
        for (int j = 0; j < 4; j++) cfr[i][j] = 0.0f;

    // prologue: chunk c -> buf (c+1)%3; chunks 0,1 -> bufs 1,2
#pragma unroll
    for (int g = 0; g < 2; g++) {
        const uint32_t bb = sb + ((g + 1) % 3) * BUF_STRIDE;
#pragma unroll
        for (int i = 0; i < 4; i++) cp16(bb + dA[i], srcA[i] + g * 64);
#pragma unroll
        for (int i = 0; i < 2; i++) cp16(bb + dB[i], srcB[i] + g * 64);
        CP_COMMIT();
    }

    for (int kc = 0; kc < 8; ++kc) {
        if (kc < 7) asm volatile("cp.async.wait_group 1;" ::: "memory");
        else        asm volatile("cp.async.wait_group 0;" ::: "memory");
        __syncthreads();
        if (kc < 6) {
            const uint32_t bb = sb + (kc % 3) * BUF_STRIDE;   // chunk kc+2
#pragma unroll
            for (int i = 0; i < 4; i++) cp16(bb + dA[i], srcA[i] + (kc + 2) * 64);
#pragma unroll
            for (int i = 0; i < 2; i++) cp16(bb + dB[i], srcB[i] + (kc + 2) * 64);
            CP_COMMIT();
        }
        const uint32_t base = sb + ((kc + 1) % 3) * BUF_STRIDE;
#pragma unroll
        for (int ks = 0; ks < 4; ++ks) {
            const uint32_t ko = (uint32_t)(ks * 32);
            uint32_t af[8], bf[8];
#pragma unroll
            for (int mt = 0; mt < 2; mt++)
                ldsm4(&af[mt * 4], base + aRT[mt] + ((ko + akb0) ^ aXV[mt]));
#pragma unroll
            for (int j = 0; j < 2; j++)
                ldsm4(&bf[j * 4], base + bRT[j] + ((ko + bkb0) ^ bXV[j]));
#pragma unroll
            for (int mt = 0; mt < 2; mt++)
#pragma unroll
                for (int nt = 0; nt < 4; nt++)
                    mma16816(cfr[mt * 4 + nt], &af[mt * 4], &bf[nt * 2]);
        }
    }

    // ---- fused dense row + col sweep (registers, mask-free) ----
    float c0[8], c1[8], c2[8];
#pragma unroll
    for (int k = 0; k < 8; k++) { c0[k] = 0.f; c1[k] = 0.f; c2[k] = 0.f; }
#pragma unroll
    for (int g = 0; g < 4; g++) {
        const int mt = g >> 1, half = g & 1;
        const int rl = wm * 32 + mt * 16 + half * 8 + (lane >> 2);
        float s0 = 0, s1 = 0, s2 = 0;
#pragma unroll
        for (int nt = 0; nt < 4; nt++) {
#pragma unroll
            for (int e = 0; e < 2; e++) {
                float s = cfr[mt * 4 + nt][half * 2 + e];
                float e0 = __expf(s * 1.25f);
                float e1 = __expf(s * 1.3888889f);
                float e2 = __expf(s * 1.5625f);
                s0 += e0; s1 += e1; s2 += e2;
                c0[nt * 2 + e] += e0; c1[nt * 2 + e] += e1; c2[nt * 2 + e] += e2;
            }
        }
#pragma unroll
        for (int o = 1; o <= 2; o <<= 1) {
            s0 += __shfl_xor_sync(0xffffffffu, s0, o);
            s1 += __shfl_xor_sync(0xffffffffu, s1, o);
            s2 += __shfl_xor_sync(0xffffffffu, s2, o);
        }
        if ((lane & 3) == 0) {
            float* d = &sAcc[wn * 1024 + rl * 8];
            d[0] = s0; d[1] = s1; d[2] = s2;
        }
    }
    // reduce col partials across lane quads (rows), accumulate into colAcc
#pragma unroll
    for (int k = 0; k < 8; k++) {
#pragma unroll
        for (int o = 4; o <= 16; o <<= 1) {
            c0[k] += __shfl_xor_sync(0xffffffffu, c0[k], o);
            c1[k] += __shfl_xor_sync(0xffffffffu, c1[k], o);
            c2[k] += __shfl_xor_sync(0xffffffffu, c2[k], o);
        }
    }
    if (lane < 4) {
#pragma unroll
        for (int k = 0; k < 8; k++) {
            const int col = wn * 32 + (k >> 1) * 8 + lane * 2 + (k & 1);
            atomicAdd(&colAcc[col * 3 + 0], c0[k]);
            atomicAdd(&colAcc[col * 3 + 1], c1[k]);
            atomicAdd(&colAcc[col * 3 + 2], c2[k]);
        }
    }

    // ---- dump C fragments to smem [128][CSTRIDE] (sparse sweeps need raw s) ----
#pragma unroll
    for (int mt = 0; mt < 2; mt++) {
#pragma unroll
        for (int half = 0; half < 2; half++) {
            const int row = wm * 32 + mt * 16 + half * 8 + (lane >> 2);
#pragma unroll
            for (int nt = 0; nt < 4; nt++) {
                const int col = wn * 32 + nt * 8 + (lane & 3) * 2;
                *(float2*)&Cs[row * CSTRIDE + col] =
                    make_float2(cfr[mt * 4 + nt][half * 2], cfr[mt * 4 + nt][half * 2 + 1]);
            }
        }
    }
    __syncthreads();

    // ---- sparse row-masked stats: thread (r = tid>>1, hr = tid&1) ----
    {
        const int r = tid >> 1, hr = tid & 1;
        float w0 = 0, w1 = 0, w2 = 0, w3 = 0, w4 = 0;
        unsigned hits = rw0 | rw1 | rw2;
        while (hits) {
            const int b = __ffs(hits) - 1;
            hits &= hits - 1;
            float s = Cs[r * CSTRIDE + hr * 32 + b];
            float e0 = __expf(s * 1.25f);
            float e1 = __expf(s * 1.3888889f);
            float e2 = __expf(s * 1.5625f);
            const unsigned bm = 1u << b;
            if (rw0 & bm) { w0 += e0; if (adjTypeR) w3 += e2; }
            if (rw1 & bm) { w1 += e0; if (adjTypeR) w4 += e1; }
            if (rw2 & bm) { w2 += e0; if (!adjTypeR) { w3 += e2; w4 += e1; } }
        }
        w0 += __shfl_xor_sync(0xffffffffu, w0, 1);
        w1 += __shfl_xor_sync(0xffffffffu, w1, 1);
        w2 += __shfl_xor_sync(0xffffffffu, w2, 1);
        w3 += __shfl_xor_sync(0xffffffffu, w3, 1);
        w4 += __shfl_xor_sync(0xffffffffu, w4, 1);
        if (hr == 0) {
            float* d = &sAcc[r * 8];   // bank 0, slots 3..7
            d[3] = w0; d[4] = w1; d[5] = w2; d[6] = w3; d[7] = w4;
        }
    }

    // ---- sparse col-masked stats, only when doCol ----
    if (doCol) {
        const int c = tid >> 2, h = tid & 3;
        const int cg = Jh * 64 + c;
        float w0 = 0, w1 = 0, w2 = 0, w3 = 0, w4 = 0;
        unsigned hits = cw0 | cw1 | cw2;
        while (hits) {
            const int b = __ffs(hits) - 1;
            hits &= hits - 1;
            float s = Cs[(h * 32 + b) * CSTRIDE + c];
            float e0 = __expf(s * 1.25f);
            float e1 = __expf(s * 1.3888889f);
            float e2 = __expf(s * 1.5625f);
            const unsigned bm = 1u << b;
            if (cw0 & bm) { w0 += e0; if (adjTypeC) w3 += e2; }
            if (cw1 & bm) { w1 += e0; if (adjTypeC) w4 += e1; }
            if (cw2 & bm) { w2 += e0; if (!adjTypeC) { w3 += e2; w4 += e1; } }
        }
#pragma unroll
        for (int o = 1; o <= 2; o <<= 1) {
            w0 += __shfl_xor_sync(0xffffffffu, w0, o);
            w1 += __shfl_xor_sync(0xffffffffu, w1, o);
            w2 += __shfl_xor_sync(0xffffffffu, w2, o);
            w3 += __shfl_xor_sync(0xffffffffu, w3, o);
            w4 += __shfl_xor_sync(0xffffffffu, w4, o);
        }
        if (h == 0) {
            const int wOffC[3] = {12, 22, 27};
            atomicAdd(&g_acc[(wOffC[pass] + 0) * N + cg], w0);
            atomicAdd(&g_acc[(wOffC[pass] + 1) * N + cg], w1);
            atomicAdd(&g_acc[(wOffC[pass] + 2) * N + cg], w2);
            atomicAdd(&g_acc[(wOffC[pass] + 3) * N + cg], w3);
            atomicAdd(&g_acc[(wOffC[pass] + 4) * N + cg], w4);
        }
    }
    __syncthreads();   // sAcc + colAcc complete

    // ---- flush row stats ----
    const int sOffR[3] = {0, 6, 3};
    const int wOffR[3] = {12, 22, 17};
#pragma unroll
    for (int v = 0; v < 4; v++) {
        const int slot = tid * 4 + v;
        const int row = slot >> 3, st = slot & 7;
        const float val = (st < 3) ? (sAcc[slot] + sAcc[1024 + slot]) : sAcc[slot];
        const int off = (st < 3) ? (sOffR[pass] + st) : (wOffR[pass] + st - 3);
        atomicAdd(&g_acc[off * N + I * 128 + row], val);
    }
    // ---- flush col dense sums ----
    if (doCol && tid < 192) {
        const int sOffC[3] = {0, 6, 9};
        const int col = tid / 3, temp = tid - col * 3;
        atomicAdd(&g_acc[(sOffC[pass] + temp) * N + Jh * 64 + col], colAcc[tid]);
    }
}

// ---------------- final reduction (shuffle-based) ----------------
__global__ void final_partial_kernel() {
    const int t = threadIdx.x;  // 128
    const int lane = t & 31, w = t >> 5;
    const int i = blockIdx.x * 128 + t;
    const float invT[3] = {1.0f / 0.8f, 1.0f / 0.72f, 1.0f / 0.64f};

    const float* sI1 = g_acc + 0 * N;  const float* sX12 = g_acc + 3 * N;
    const float* sI2 = g_acc + 6 * N;  const float* sX21 = g_acc + 9 * N;
    const float* wI1 = g_acc + 12 * N; const float* wX12 = g_acc + 17 * N;
    const float* wI2 = g_acc + 22 * N; const float* wX21 = g_acc + 27 * N;
    const float* rA = g_acc + 32 * N;  const float* rG = g_acc + 35 * N;
    const float* d12 = g_acc + 40 * N;

    const int ktau[5] = {0, 0, 0, 2, 1};
    const int kadj1[5] = {0, 1, 2, 0, 1};
    const int kadj2[5] = {0, 1, 2, 2, 2};

    float p[13];
    {
        float eD[3], e12[3];
#pragma unroll
        for (int tt = 0; tt < 3; tt++) {
            eD[tt] = expf(invT[tt]);               // diag(S11)=diag(S22)=1
            e12[tt] = expf(d12[i] * invT[tt]);
        }
#pragma unroll
        for (int k = 0; k < 5; k++) {
            int tt = ktau[k];
            float pos = e12[tt] + wI1[k * N + i] + wX12[k * N + i];
            float den = sI1[tt * N + i] + sX12[tt * N + i] - eD[tt];
            p[k] = logf(pos / den) / (2.0f * rA[kadj1[k] * N + i] + 1.0f);
        }
#pragma unroll
        for (int k = 0; k < 5; k++) {
            int tt = ktau[k];
            float pos = e12[tt] + wI2[k * N + i] + wX21[k * N + i];
            float den = sI2[tt * N + i] + sX21[tt * N + i] - eD[tt];
            p[5 + k] = logf(pos / den) / (2.0f * rG[kadj2[k] * N + i] + 1.0f);
        }
        p[10] = rA[0 * N + i]; p[11] = rA[1 * N + i]; p[12] = rA[2 * N + i];
    }

    __shared__ float part[4][13];
#pragma unroll
    for (int v = 0; v < 13; v++) {
        float x = p[v];
#pragma unroll
        for (int o = 16; o; o >>= 1) x += __shfl_xor_sync(0xffffffffu, x, o);
        if (lane == 0) part[w][v] = x;
    }
    __syncthreads();
    if (t < 13) {
        atomicAdd(&g_tot[t], part[0][t] + part[1][t] + part[2][t] + part[3][t]);
    }
}

__global__ void combine_kernel(float* __restrict__ out) {
    float L1[5], L2[5];
#pragma unroll
    for (int k = 0; k < 5; k++) {
        L1[k] = -g_tot[k] / (float)N;
        L2[k] = -g_tot[5 + k] / (float)N;
    }
    float Lc = 0.55f * L1[0] + 0.4f * L2[0];
    float Lm = 0.55f * L1[1] + 0.4f * L2[1];
    float Lf = 0.55f * L1[2] + 0.4f * L2[2];
    float Lcf = 0.55f * L1[3] + 0.4f * L2[3];
    float Lmf = 0.55f * L1[4] + 0.4f * L2[4];
    float sc = g_tot[10], sm = g_tot[11], sf = g_tot[12];
    float total = sc + sm + sf + 1e-8f;
    out[0] = (sc * Lc + sm * Lm + sf * Lf) / total + 0.2f * (Lcf + Lmf);
}

// ---------------- launch ----------------
extern "C" void kernel_launch(void* const* d_in, const int* in_sizes, int n_in,
                              void* d_out, int out_size) {
    const float* z1 = (const float*)d_in[0];
    const float* z2 = (const float*)d_in[1];

    cudaFuncSetAttribute(gram_kernel, cudaFuncAttributeMaxDynamicSharedMemorySize,
                         SMEM_BYTES);

    zero_acc_kernel<<<(ACC_TOTAL + 255) / 256, 256>>>();
    pack_adj_kernel<<<dim3(N, 6), 128>>>(
        (const float*)d_in[2], (const float*)d_in[3], (const float*)d_in[4],
        (const float*)d_in[5], (const float*)d_in[6], (const float*)d_in[7]);
    normalize_kernel<<<dim3(N, 2), 128>>>(z1, z2);
    diag12_kernel<<<N, 128>>>();
    gram_kernel<<<GRID_TILES, 256, SMEM_BYTES>>>();
    final_partial_kernel<<<32, 128>>>();
    combine_kernel<<<1, 1>>>((float*)d_out);
}

// round 16
// speedup vs baseline: 1.0169x; 1.0169x over previous
#include <cuda_runtime.h>
#include <cuda_fp16.h>
#include <math.h>
#include <stdint.h>

#define N 4096
#define D 512
#define NT 32
#define SYM_TILES 1056                    // sum_{I=0}^{31} (64 - 2I)
#define GRID_TILES (SYM_TILES * 2 + 2048) // 4160

// ---------------- device scratch ----------------
__device__ __half g_h1[N * D];
__device__ __half g_h2[N * D];
__device__ unsigned g_bits[6][N][128];   // bit-packed adjacency (12.6 MB)

// Accumulator layout (row-indexed, length N each):
//  0..2 sI1, 3..5 sX12, 6..8 sI2, 9..11 sX21,
//  12..16 wI1, 17..21 wX12, 22..26 wI2, 27..31 wX21,
//  32..34 rA, 35..37 rG, 38 d11, 39 d22, 40 d12
#define ACC_TOTAL (41 * N)
__device__ float g_acc[ACC_TOTAL];
__device__ float g_tot[13];

// smem: 3 buffers x (A 16KB + B 8KB) = 73728. Post-MMA C[128][72] (36864 B)
// occupies buf0 + low half of buf1; rotated chunk->buffer mapping puts the
// final k-chunk in buf2, so the dump never races in-flight ldsm.
// Stat acc: 2 banks x 4KB at 73728.
#define BUF_STRIDE 24576
#define SACC_OFF 73728
#define SMEM_BYTES (73728 + 8192)
#define CSTRIDE 72

#define SWZ(o) ((o) ^ (((o) >> 3) & 0x70))

// ---------------- PTX helpers ----------------
__device__ __forceinline__ uint32_t smem_u32_of(const void* p) {
    uint32_t a;
    asm("{ .reg .u64 t; cvta.to.shared.u64 t, %1; cvt.u32.u64 %0, t; }" : "=r"(a) : "l"(p));
    return a;
}
__device__ __forceinline__ void ldsm4(uint32_t* r, uint32_t addr) {
    asm volatile("ldmatrix.sync.aligned.m8n8.x4.shared.b16 {%0,%1,%2,%3}, [%4];"
                 : "=r"(r[0]), "=r"(r[1]), "=r"(r[2]), "=r"(r[3]) : "r"(addr));
}
__device__ __forceinline__ void mma16816(float* c, const uint32_t* a, const uint32_t* b) {
    asm volatile(
        "mma.sync.aligned.m16n8k16.row.col.f32.f16.f16.f32 "
        "{%0,%1,%2,%3}, {%4,%5,%6,%7}, {%8,%9}, {%0,%1,%2,%3};"
        : "+f"(c[0]), "+f"(c[1]), "+f"(c[2]), "+f"(c[3])
        : "r"(a[0]), "r"(a[1]), "r"(a[2]), "r"(a[3]), "r"(b[0]), "r"(b[1]));
}
__device__ __forceinline__ void cp16(uint32_t dst, const void* src) {
    asm volatile("cp.async.cg.shared.global [%0], [%1], 16;" :: "r"(dst), "l"(src));
}
#define CP_COMMIT() asm volatile("cp.async.commit_group;" ::: "memory")

// ---------------- small kernels ----------------
__global__ void zero_acc_kernel() {
    int i = blockIdx.x * blockDim.x + threadIdx.x;
    if (i < ACC_TOTAL) g_acc[i] = 0.0f;
    if (i < 13) g_tot[i] = 0.0f;
}

// Bit-pack adjacency + row sums. grid(N, 6), block 128, float4 loads.
__global__ void pack_adj_kernel(const float* __restrict__ a0, const float* __restrict__ a1,
                                const float* __restrict__ a2, const float* __restrict__ a3,
                                const float* __restrict__ a4, const float* __restrict__ a5) {
    const int row = blockIdx.x, mat = blockIdx.y, t = threadIdx.x;
    const float* src;
    switch (mat) {
        case 0: src = a0; break; case 1: src = a1; break; case 2: src = a2; break;
        case 3: src = a3; break; case 4: src = a4; break; default: src = a5; break;
    }
    const int lane = t & 31, w = t >> 5;
    int cnt = 0;
#pragma unroll
    for (int it = 0; it < 8; it++) {
        float4 v = *(const float4*)(src + (size_t)row * N + it * 512 + t * 4);
        unsigned nib = (unsigned)(v.x != 0.0f) | ((unsigned)(v.y != 0.0f) << 1) |
                       ((unsigned)(v.z != 0.0f) << 2) | ((unsigned)(v.w != 0.0f) << 3);
        cnt += __popc(nib);
        unsigned val = nib << (4 * (t & 7));
        val |= __shfl_xor_sync(0xffffffffu, val, 1);
        val |= __shfl_xor_sync(0xffffffffu, val, 2);
        val |= __shfl_xor_sync(0xffffffffu, val, 4);
        if ((t & 7) == 0) g_bits[mat][row][it * 16 + (t >> 3)] = val;
    }
#pragma unroll
    for (int o = 16; o; o >>= 1) cnt += __shfl_xor_sync(0xffffffffu, cnt, o);
    __shared__ int sc[4];
    if (lane == 0) sc[w] = cnt;
    __syncthreads();
    if (t == 0)
        g_acc[(32 + mat) * N + row] = (float)(sc[0] + sc[1] + sc[2] + sc[3]);
}

// Normalize fp32 -> fp16. grid(N,2), block 128.
__global__ void normalize_kernel(const float* __restrict__ z1,
                                 const float* __restrict__ z2) {
    int row = blockIdx.x;
    const float* src = (blockIdx.y == 0) ? z1 : z2;
    __half* dst = (blockIdx.y == 0) ? g_h1 : g_h2;
    int t = threadIdx.x;

    float4 v = ((const float4*)(src + (size_t)row * D))[t];
    float s = v.x * v.x + v.y * v.y + v.z * v.z + v.w * v.w;
#pragma unroll
    for (int o = 16; o; o >>= 1) s += __shfl_xor_sync(0xffffffffu, s, o);
    __shared__ float ws[4];
    if ((t & 31) == 0) ws[t >> 5] = s;
    __syncthreads();
    float inv = 1.0f / fmaxf(sqrtf(ws[0] + ws[1] + ws[2] + ws[3]), 1e-12f);
    size_t base = (size_t)row * D + t * 4;
    dst[base + 0] = __float2half_rn(v.x * inv);
    dst[base + 1] = __float2half_rn(v.y * inv);
    dst[base + 2] = __float2half_rn(v.z * inv);
    dst[base + 3] = __float2half_rn(v.w * inv);
}

// ---------------- gram kernel ----------------
// 1D grid over 4160 tiles of 128 rows x 64 cols. 256 thr, 8 warps (4x2),
// warp tile 32x32. Dense sweeps mask-free; masked stats via union-bitmask
// + ffs sparse loops over the smem C dump (density ~0.5%).
__global__ void __launch_bounds__(256, 2) gram_kernel() {
    extern __shared__ char smem[];
    float* Cs = (float*)smem;                  // post-MMA reuse, [128][72]
    float* sAcc = (float*)(smem + SACC_OFF);   // [2][128][8]
    const uint32_t sb = smem_u32_of(smem);
    const int tid = threadIdx.x, lane = tid & 31, wid = tid >> 5;
    const int wm = wid & 3, wn = wid >> 2;

    // ---- decode (pass, I, Jh) ----
    int pass, I, Jh;
    {
        int t = blockIdx.x;
        if (t < 2 * SYM_TILES) {
            pass = (t < SYM_TILES) ? 0 : 1;
            int rem = t - pass * SYM_TILES;
            int i = 0;
            while (rem >= 64 - 2 * i) { rem -= 64 - 2 * i; i++; }
            I = i; Jh = 2 * i + rem;
        } else {
            pass = 2;
            int u = t - 2 * SYM_TILES;
            I = u >> 6; Jh = u & 63;
        }
    }
    const bool diagBlock = ((Jh >> 1) == I);
    const bool doCol = (pass == 2) || (Jh >= 2 * I + 2);
    const bool adjTypeR = (pass != 1);
    const bool adjTypeC = (pass == 0);
    const int mbR = adjTypeR ? 0 : 3;
    const int mbC = adjTypeC ? 0 : 3;

    // ---- hoisted sparse-mask words (LDG latency overlaps MMA phase) ----
    const int rsRow = I * 128 + (tid >> 1);
    const int rsWord = Jh * 2 + (tid & 1);
    unsigned rw0 = g_bits[mbR + 0][rsRow][rsWord];
    unsigned rw1 = g_bits[mbR + 1][rsRow][rsWord];
    unsigned rw2 = g_bits[mbR + 2][rsRow][rsWord];
    const int csCol = Jh * 64 + (tid >> 2);
    unsigned cw0 = 0, cw1 = 0, cw2 = 0;
    if (doCol) {
        cw0 = g_bits[mbC + 0][csCol][I * 4 + (tid & 3)];
        cw1 = g_bits[mbC + 1][csCol][I * 4 + (tid & 3)];
        cw2 = g_bits[mbC + 2][csCol][I * 4 + (tid & 3)];
    }

    // ldmatrix lane addressing
    const int arow = wm * 32 + (lane & 15);
    const uint32_t akb0 = (uint32_t)((lane >> 4) * 16);
    const int brow = wn * 32 + ((lane >> 4) * 8) + (lane & 7);
    const uint32_t bkb0 = (uint32_t)(((lane >> 3) & 1) * 16);
    uint32_t aRT[2], aXV[2], bRT[2], bXV[2];
#pragma unroll
    for (int mt = 0; mt < 2; mt++) {
        int r = arow + mt * 16;
        aRT[mt] = (uint32_t)(r * 128);
        aXV[mt] = (uint32_t)((r & 7) << 4);
    }
#pragma unroll
    for (int j = 0; j < 2; j++) {
        int r = brow + j * 16;
        bRT[j] = (uint32_t)(16384 + r * 128);
        bXV[j] = (uint32_t)((r & 7) << 4);
    }

    // staging decomposition: A = 1024 16B units (4/thread), B = 512 (2/thread)
    const int sRow[4] = {(tid + 0) >> 3, (tid + 256) >> 3, (tid + 512) >> 3, (tid + 768) >> 3};
    const int sSeg[4] = {(tid + 0) & 7, (tid + 256) & 7, (tid + 512) & 7, (tid + 768) & 7};
    uint32_t dA[4], dB[2];
#pragma unroll
    for (int i = 0; i < 4; i++) dA[i] = SWZ((uint32_t)(sRow[i] * 128 + sSeg[i] * 16));
#pragma unroll
    for (int i = 0; i < 2; i++)
        dB[i] = 16384u + SWZ((uint32_t)((sRow[i] & 63) * 128 + sSeg[i] * 16));

    const __half* Ap = (pass == 1) ? g_h2 : g_h1;
    const __half* Bp = (pass == 0) ? g_h1 : g_h2;
    const __half* Ag = Ap + (size_t)I * 128 * D;
    const __half* Bg = Bp + (size_t)Jh * 64 * D;
    const __half* srcA[4];
    const __half* srcB[2];
#pragma unroll
    for (int i = 0; i < 4; i++) srcA[i] = Ag + (size_t)sRow[i] * D + sSeg[i] * 8;
#pragma unroll
    for (int i = 0; i < 2; i++) srcB[i] = Bg + (size_t)(sRow[i] & 63) * D + sSeg[i] * 8;

    float cfr[8][4];
#pragma unroll
    for (int i = 0; i < 8; i++)
#pragma unroll
        for (int j = 0; j < 4; j++) cfr[i][j] = 0.0f;

    // prologue: chunk c -> buf (c+1)%3; chunks 0,1 -> bufs 1,2
#pragma unroll
    for (int g = 0; g < 2; g++) {
        const uint32_t bb = sb + ((g + 1) % 3) * BUF_STRIDE;
#pragma unroll
        for (int i = 0; i < 4; i++) cp16(bb + dA[i], srcA[i] + g * 64);
#pragma unroll
        for (int i = 0; i < 2; i++) cp16(bb + dB[i], srcB[i] + g * 64);
        CP_COMMIT();
    }

    for (int kc = 0; kc < 8; ++kc) {
        if (kc < 7) asm volatile("cp.async.wait_group 1;" ::: "memory");
        else        asm volatile("cp.async.wait_group 0;" ::: "memory");
        __syncthreads();
        if (kc < 6) {
            const uint32_t bb = sb + (kc % 3) * BUF_STRIDE;   // chunk kc+2 -> buf (kc+3)%3
#pragma unroll
            for (int i = 0; i < 4; i++) cp16(bb + dA[i], srcA[i] + (kc + 2) * 64);
#pragma unroll
            for (int i = 0; i < 2; i++) cp16(bb + dB[i], srcB[i] + (kc + 2) * 64);
            CP_COMMIT();
        }
        const uint32_t base = sb + ((kc + 1) % 3) * BUF_STRIDE;
#pragma unroll
        for (int ks = 0; ks < 4; ++ks) {
            const uint32_t ko = (uint32_t)(ks * 32);
            uint32_t af[8], bf[8];
#pragma unroll
            for (int mt = 0; mt < 2; mt++)
                ldsm4(&af[mt * 4], base + aRT[mt] + ((ko + akb0) ^ aXV[mt]));
#pragma unroll
            for (int j = 0; j < 2; j++)
                ldsm4(&bf[j * 4], base + bRT[j] + ((ko + bkb0) ^ bXV[j]));
#pragma unroll
            for (int mt = 0; mt < 2; mt++)
#pragma unroll
                for (int nt = 0; nt < 4; nt++)
                    mma16816(cfr[mt * 4 + nt], &af[mt * 4], &bf[nt * 2]);
        }
    }

    // ---- dense row epilogue (registers, mask-free) ----
#pragma unroll
    for (int g = 0; g < 4; g++) {
        const int mt = g >> 1, half = g & 1;
        const int rl = wm * 32 + mt * 16 + half * 8 + (lane >> 2);
        float s0 = 0, s1 = 0, s2 = 0;
#pragma unroll
        for (int nt = 0; nt < 4; nt++) {
#pragma unroll
            for (int e = 0; e < 2; e++) {
                float s = cfr[mt * 4 + nt][half * 2 + e];
                s0 += __expf(s * 1.25f);
                s1 += __expf(s * 1.3888889f);
                s2 += __expf(s * 1.5625f);
            }
        }
#pragma unroll
        for (int o = 1; o <= 2; o <<= 1) {
            s0 += __shfl_xor_sync(0xffffffffu, s0, o);
            s1 += __shfl_xor_sync(0xffffffffu, s1, o);
            s2 += __shfl_xor_sync(0xffffffffu, s2, o);
        }
        if ((lane & 3) == 0) {
            float* d = &sAcc[wn * 1024 + rl * 8];
            d[0] = s0; d[1] = s1; d[2] = s2;
        }
    }

    // ---- diag extraction (rare uniform branch) ----
    if (diagBlock) {
        const int off = (Jh & 1) * 64;
#pragma unroll
        for (int g = 0; g < 4; g++) {
            const int rl = wm * 32 + (g >> 1) * 16 + (g & 1) * 8 + (lane >> 2);
#pragma unroll
            for (int nt = 0; nt < 4; nt++)
#pragma unroll
                for (int e = 0; e < 2; e++) {
                    const int cl = wn * 32 + nt * 8 + (lane & 3) * 2 + e;
                    if (rl == off + cl)
                        g_acc[(38 + pass) * N + I * 128 + rl] =
                            cfr[(g >> 1) * 4 + nt][(g & 1) * 2 + e];
                }
        }
    }

    // ---- dump C fragments to smem [128][CSTRIDE] ----
#pragma unroll
    for (int mt = 0; mt < 2; mt++) {
#pragma unroll
        for (int half = 0; half < 2; half++) {
            const int row = wm * 32 + mt * 16 + half * 8 + (lane >> 2);
#pragma unroll
            for (int nt = 0; nt < 4; nt++) {
                const int col = wn * 32 + nt * 8 + (lane & 3) * 2;
                *(float2*)&Cs[row * CSTRIDE + col] =
                    make_float2(cfr[mt * 4 + nt][half * 2], cfr[mt * 4 + nt][half * 2 + 1]);
            }
        }
    }
    __syncthreads();

    // ---- sparse row-masked stats: thread (r = tid>>1, hr = tid&1) ----
    {
        const int r = tid >> 1, hr = tid & 1;
        float w0 = 0, w1 = 0, w2 = 0, w3 = 0, w4 = 0;
        unsigned hits = rw0 | rw1 | rw2;
        while (hits) {
            const int b = __ffs(hits) - 1;
            hits &= hits - 1;
            float s = Cs[r * CSTRIDE + hr * 32 + b];
            float e0 = __expf(s * 1.25f);
            float e1 = __expf(s * 1.3888889f);
            float e2 = __expf(s * 1.5625f);
            const unsigned bm = 1u << b;
            if (rw0 & bm) { w0 += e0; if (adjTypeR) w3 += e2; }
            if (rw1 & bm) { w1 += e0; if (adjTypeR) w4 += e1; }
            if (rw2 & bm) { w2 += e0; if (!adjTypeR) { w3 += e2; w4 += e1; } }
        }
        w0 += __shfl_xor_sync(0xffffffffu, w0, 1);
        w1 += __shfl_xor_sync(0xffffffffu, w1, 1);
        w2 += __shfl_xor_sync(0xffffffffu, w2, 1);
        w3 += __shfl_xor_sync(0xffffffffu, w3, 1);
        w4 += __shfl_xor_sync(0xffffffffu, w4, 1);
        if (hr == 0) {
            float* d = &sAcc[r * 8];   // bank 0, slots 3..7
            d[3] = w0; d[4] = w1; d[5] = w2; d[6] = w3; d[7] = w4;
        }
    }

    // ---- column stats (dense + sparse), only when doCol ----
    if (doCol) {
        const int c = tid >> 2, h = tid & 3;
        const int cg = Jh * 64 + c;
        float s0 = 0, s1 = 0, s2 = 0, w0 = 0, w1 = 0, w2 = 0, w3 = 0, w4 = 0;
        // dense: rows h, h+4, ..., h+124 (conflict-free LDS)
#pragma unroll 8
        for (int k = 0; k < 32; k++) {
            float s = Cs[(h + 4 * k) * CSTRIDE + c];
            s0 += __expf(s * 1.25f);
            s1 += __expf(s * 1.3888889f);
            s2 += __expf(s * 1.5625f);
        }
        // sparse masked: word q = h covers rows [32h, 32h+32)
        unsigned hits = cw0 | cw1 | cw2;
        while (hits) {
            const int b = __ffs(hits) - 1;
            hits &= hits - 1;
            float s = Cs[(h * 32 + b) * CSTRIDE + c];
            float e0 = __expf(s * 1.25f);
            float e1 = __expf(s * 1.3888889f);
            float e2 = __expf(s * 1.5625f);
            const unsigned bm = 1u << b;
            if (cw0 & bm) { w0 += e0; if (adjTypeC) w3 += e2; }
            if (cw1 & bm) { w1 += e0; if (adjTypeC) w4 += e1; }
            if (cw2 & bm) { w2 += e0; if (!adjTypeC) { w3 += e2; w4 += e1; } }
        }
#pragma unroll
        for (int o = 1; o <= 2; o <<= 1) {
            s0 += __shfl_xor_sync(0xffffffffu, s0, o);
            s1 += __shfl_xor_sync(0xffffffffu, s1, o);
            s2 += __shfl_xor_sync(0xffffffffu, s2, o);
            w0 += __shfl_xor_sync(0xffffffffu, w0, o);
            w1 += __shfl_xor_sync(0xffffffffu, w1, o);
            w2 += __shfl_xor_sync(0xffffffffu, w2, o);
            w3 += __shfl_xor_sync(0xffffffffu, w3, o);
            w4 += __shfl_xor_sync(0xffffffffu, w4, o);
        }
        if (h == 0) {
            const int sOffC[3] = {0, 6, 9};
            const int wOffC[3] = {12, 22, 27};
            atomicAdd(&g_acc[(sOffC[pass] + 0) * N + cg], s0);
            atomicAdd(&g_acc[(sOffC[pass] + 1) * N + cg], s1);
            atomicAdd(&g_acc[(sOffC[pass] + 2) * N + cg], s2);
            atomicAdd(&g_acc[(wOffC[pass] + 0) * N + cg], w0);
            atomicAdd(&g_acc[(wOffC[pass] + 1) * N + cg], w1);
            atomicAdd(&g_acc[(wOffC[pass] + 2) * N + cg], w2);
            atomicAdd(&g_acc[(wOffC[pass] + 3) * N + cg], w3);
            atomicAdd(&g_acc[(wOffC[pass] + 4) * N + cg], w4);
        }
    }
    __syncthreads();   // sAcc complete (dense banks + sparse slots)

    // ---- flush row stats: slots 0-2 sum 2 banks, slots 3-7 bank 0 only ----
    const int sOffR[3] = {0, 6, 3};
    const int wOffR[3] = {12, 22, 17};
#pragma unroll
    for (int v = 0; v < 4; v++) {
        const int slot = tid * 4 + v;
        const int row = slot >> 3, st = slot & 7;
        const float val = (st < 3) ? (sAcc[slot] + sAcc[1024 + slot]) : sAcc[slot];
        const int off = (st < 3) ? (sOffR[pass] + st) : (wOffR[pass] + st - 3);
        atomicAdd(&g_acc[off * N + I * 128 + row], val);
    }
}

// ---------------- final reduction (shuffle-based) ----------------
__global__ void final_partial_kernel() {
    const int t = threadIdx.x;  // 128
    const int lane = t & 31, w = t >> 5;
    const int i = blockIdx.x * 128 + t;
    const float invT[3] = {1.0f / 0.8f, 1.0f / 0.72f, 1.0f / 0.64f};

    const float* sI1 = g_acc + 0 * N;  const float* sX12 = g_acc + 3 * N;
    const float* sI2 = g_acc + 6 * N;  const float* sX21 = g_acc + 9 * N;
    const float* wI1 = g_acc + 12 * N; const float* wX12 = g_acc + 17 * N;
    const float* wI2 = g_acc + 22 * N; const float* wX21 = g_acc + 27 * N;
    const float* rA = g_acc + 32 * N;  const float* rG = g_acc + 35 * N;
    const float* d11 = g_acc + 38 * N; const float* d22 = g_acc + 39 * N;
    const float* d12 = g_acc + 40 * N;

    const int ktau[5] = {0, 0, 0, 2, 1};
    const int kadj1[5] = {0, 1, 2, 0, 1};
    const int kadj2[5] = {0, 1, 2, 2, 2};

    float p[13];
    {
        float e11[3], e22[3], e12[3];
#pragma unroll
        for (int tt = 0; tt < 3; tt++) {
            e11[tt] = expf(d11[i] * invT[tt]);
            e22[tt] = expf(d22[i] * invT[tt]);
            e12[tt] = expf(d12[i] * invT[tt]);
        }
#pragma unroll
        for (int k = 0; k < 5; k++) {
            int tt = ktau[k];
            float pos = e12[tt] + wI1[k * N + i] + wX12[k * N + i];
            float den = sI1[tt * N + i] + sX12[tt * N + i] - e11[tt];
            p[k] = logf(pos / den) / (2.0f * rA[kadj1[k] * N + i] + 1.0f);
        }
#pragma unroll
        for (int k = 0; k < 5; k++) {
            int tt = ktau[k];
            float pos = e12[tt] + wI2[k * N + i] + wX21[k * N + i];
            float den = sI2[tt * N + i] + sX21[tt * N + i] - e22[tt];
            p[5 + k] = logf(pos / den) / (2.0f * rG[kadj2[k] * N + i] + 1.0f);
        }
        p[10] = rA[0 * N + i]; p[11] = rA[1 * N + i]; p[12] = rA[2 * N + i];
    }

    __shared__ float part[4][13];
#pragma unroll
    for (int v = 0; v < 13; v++) {
        float x = p[v];
#pragma unroll
        for (int o = 16; o; o >>= 1) x += __shfl_xor_sync(0xffffffffu, x, o);
        if (lane == 0) part[w][v] = x;
    }
    __syncthreads();
    if (t < 13) {
        atomicAdd(&g_tot[t], part[0][t] + part[1][t] + part[2][t] + part[3][t]);
    }
}

__global__ void combine_kernel(float* __restrict__ out) {
    float L1[5], L2[5];
#pragma unroll
    for (int k = 0; k < 5; k++) {
        L1[k] = -g_tot[k] / (float)N;
        L2[k] = -g_tot[5 + k] / (float)N;
    }
    float Lc = 0.55f * L1[0] + 0.4f * L2[0];
    float Lm = 0.55f * L1[1] + 0.4f * L2[1];
    float Lf = 0.55f * L1[2] + 0.4f * L2[2];
    float Lcf = 0.55f * L1[3] + 0.4f * L2[3];
    float Lmf = 0.55f * L1[4] + 0.4f * L2[4];
    float sc = g_tot[10], sm = g_tot[11], sf = g_tot[12];
    float total = sc + sm + sf + 1e-8f;
    out[0] = (sc * Lc + sm * Lm + sf * Lf) / total + 0.2f * (Lcf + Lmf);
}

// ---------------- launch ----------------
extern "C" void kernel_launch(void* const* d_in, const int* in_sizes, int n_in,
                              void* d_out, int out_size) {
    const float* z1 = (const float*)d_in[0];
    const float* z2 = (const float*)d_in[1];

    cudaFuncSetAttribute(gram_kernel, cudaFuncAttributeMaxDynamicSharedMemorySize,
                         SMEM_BYTES);

    zero_acc_kernel<<<(ACC_TOTAL + 255) / 256, 256>>>();
    pack_adj_kernel<<<dim3(N, 6), 128>>>(
        (const float*)d_in[2], (const float*)d_in[3], (const float*)d_in[4],
        (const float*)d_in[5], (const float*)d_in[6], (const float*)d_in[7]);
    normalize_kernel<<<dim3(N, 2), 128>>>(z1, z2);
    gram_kernel<<<GRID_TILES, 256, SMEM_BYTES>>>();
    final_partial_kernel<<<32, 128>>>();
    combine_kernel<<<1, 1>>>((float*)d_out);
}

// round 17
// speedup vs baseline: 1.0811x; 1.0631x over previous
#include <cuda_runtime.h>
#include <cuda_fp16.h>
#include <math.h>
#include <stdint.h>

#define N 4096
#define D 512
#define NT 32
#define SYM_TILES 1056                    // sum_{I=0}^{31} (64 - 2I)
#define GRID_TILES (SYM_TILES * 2 + 2048) // 4160

// ---------------- device scratch ----------------
__device__ __half g_h1[N * D];
__device__ __half g_h2[N * D];
__device__ unsigned g_bits[6][N][128];   // bit-packed adjacency (12.6 MB)

// Accumulator layout (row-indexed, length N each):
//  0..2 sI1, 3..5 sX12, 6..8 sI2, 9..11 sX21,
//  12..16 wI1, 17..21 wX12, 22..26 wI2, 27..31 wX21,
//  32..34 rA, 35..37 rG, 38 d11, 39 d22, 40 d12
#define ACC_TOTAL (41 * N)
__device__ float g_acc[ACC_TOTAL];
__device__ float g_tot[13];

// smem: 3 buffers x (A 16KB + B 8KB) = 73728 (reused as C[128][72] post-MMA;
// a __syncthreads() before the dump orders it after all ldsm reads).
// Stat acc: 2 banks x 4KB at 73728.
#define BUF_STRIDE 24576
#define SACC_OFF 73728
#define SMEM_BYTES (73728 + 8192)
#define CSTRIDE 72

#define SWZ(o) ((o) ^ (((o) >> 3) & 0x70))

// ---------------- PTX helpers ----------------
__device__ __forceinline__ uint32_t smem_u32_of(const void* p) {
    uint32_t a;
    asm("{ .reg .u64 t; cvta.to.shared.u64 t, %1; cvt.u32.u64 %0, t; }" : "=r"(a) : "l"(p));
    return a;
}
__device__ __forceinline__ void ldsm4(uint32_t* r, uint32_t addr) {
    asm volatile("ldmatrix.sync.aligned.m8n8.x4.shared.b16 {%0,%1,%2,%3}, [%4];"
                 : "=r"(r[0]), "=r"(r[1]), "=r"(r[2]), "=r"(r[3]) : "r"(addr));
}
__device__ __forceinline__ void mma16816(float* c, const uint32_t* a, const uint32_t* b) {
    asm volatile(
        "mma.sync.aligned.m16n8k16.row.col.f32.f16.f16.f32 "
        "{%0,%1,%2,%3}, {%4,%5,%6,%7}, {%8,%9}, {%0,%1,%2,%3};"
        : "+f"(c[0]), "+f"(c[1]), "+f"(c[2]), "+f"(c[3])
        : "r"(a[0]), "r"(a[1]), "r"(a[2]), "r"(a[3]), "r"(b[0]), "r"(b[1]));
}
__device__ __forceinline__ void cp16(uint32_t dst, const void* src) {
    asm volatile("cp.async.cg.shared.global [%0], [%1], 16;" :: "r"(dst), "l"(src));
}
#define CP_COMMIT() asm volatile("cp.async.commit_group;" ::: "memory")

// ---------------- small kernels ----------------
__global__ void zero_acc_kernel() {
    int i = blockIdx.x * blockDim.x + threadIdx.x;
    if (i < ACC_TOTAL) g_acc[i] = 0.0f;
    if (i < 13) g_tot[i] = 0.0f;
}

// Bit-pack adjacency + row sums. grid(N, 6), block 128, float4 loads.
__global__ void pack_adj_kernel(const float* __restrict__ a0, const float* __restrict__ a1,
                                const float* __restrict__ a2, const float* __restrict__ a3,
                                const float* __restrict__ a4, const float* __restrict__ a5) {
    const int row = blockIdx.x, mat = blockIdx.y, t = threadIdx.x;
    const float* src;
    switch (mat) {
        case 0: src = a0; break; case 1: src = a1; break; case 2: src = a2; break;
        case 3: src = a3; break; case 4: src = a4; break; default: src = a5; break;
    }
    const int lane = t & 31, w = t >> 5;
    int cnt = 0;
#pragma unroll
    for (int it = 0; it < 8; it++) {
        float4 v = *(const float4*)(src + (size_t)row * N + it * 512 + t * 4);
        unsigned nib = (unsigned)(v.x != 0.0f) | ((unsigned)(v.y != 0.0f) << 1) |
                       ((unsigned)(v.z != 0.0f) << 2) | ((unsigned)(v.w != 0.0f) << 3);
        cnt += __popc(nib);
        unsigned val = nib << (4 * (t & 7));
        val |= __shfl_xor_sync(0xffffffffu, val, 1);
        val |= __shfl_xor_sync(0xffffffffu, val, 2);
        val |= __shfl_xor_sync(0xffffffffu, val, 4);
        if ((t & 7) == 0) g_bits[mat][row][it * 16 + (t >> 3)] = val;
    }
#pragma unroll
    for (int o = 16; o; o >>= 1) cnt += __shfl_xor_sync(0xffffffffu, cnt, o);
    __shared__ int sc[4];
    if (lane == 0) sc[w] = cnt;
    __syncthreads();
    if (t == 0)
        g_acc[(32 + mat) * N + row] = (float)(sc[0] + sc[1] + sc[2] + sc[3]);
}

// Normalize fp32 -> fp16. grid(N,2), block 128.
__global__ void normalize_kernel(const float* __restrict__ z1,
                                 const float* __restrict__ z2) {
    int row = blockIdx.x;
    const float* src = (blockIdx.y == 0) ? z1 : z2;
    __half* dst = (blockIdx.y == 0) ? g_h1 : g_h2;
    int t = threadIdx.x;

    float4 v = ((const float4*)(src + (size_t)row * D))[t];
    float s = v.x * v.x + v.y * v.y + v.z * v.z + v.w * v.w;
#pragma unroll
    for (int o = 16; o; o >>= 1) s += __shfl_xor_sync(0xffffffffu, s, o);
    __shared__ float ws[4];
    if ((t & 31) == 0) ws[t >> 5] = s;
    __syncthreads();
    float inv = 1.0f / fmaxf(sqrtf(ws[0] + ws[1] + ws[2] + ws[3]), 1e-12f);
    size_t base = (size_t)row * D + t * 4;
    dst[base + 0] = __float2half_rn(v.x * inv);
    dst[base + 1] = __float2half_rn(v.y * inv);
    dst[base + 2] = __float2half_rn(v.z * inv);
    dst[base + 3] = __float2half_rn(v.w * inv);
}

// ---------------- gram kernel ----------------
// 1D grid over 4160 tiles of 128 rows x 64 cols. 256 thr, 8 warps (4x2),
// warp tile 32x32. Dense sweeps mask-free; masked stats via union-bitmask
// + ffs sparse loops over the smem C dump (density ~0.5%).
// R13 buffer mapping (compute kc%3, prefetch (kc+2)%3) + explicit barrier
// before the C dump to order it after all ldsm reads.
__global__ void __launch_bounds__(256, 2) gram_kernel() {
    extern __shared__ char smem[];
    float* Cs = (float*)smem;                  // post-MMA reuse, [128][72]
    float* sAcc = (float*)(smem + SACC_OFF);   // [2][128][8]
    const uint32_t sb = smem_u32_of(smem);
    const int tid = threadIdx.x, lane = tid & 31, wid = tid >> 5;
    const int wm = wid & 3, wn = wid >> 2;

    // ---- decode (pass, I, Jh) ----
    int pass, I, Jh;
    {
        int t = blockIdx.x;
        if (t < 2 * SYM_TILES) {
            pass = (t < SYM_TILES) ? 0 : 1;
            int rem = t - pass * SYM_TILES;
            int i = 0;
            while (rem >= 64 - 2 * i) { rem -= 64 - 2 * i; i++; }
            I = i; Jh = 2 * i + rem;
        } else {
            pass = 2;
            int u = t - 2 * SYM_TILES;
            I = u >> 6; Jh = u & 63;
        }
    }
    const bool diagBlock = ((Jh >> 1) == I);
    const bool doCol = (pass == 2) || (Jh >= 2 * I + 2);
    const bool adjTypeR = (pass != 1);
    const bool adjTypeC = (pass == 0);
    const int mbR = adjTypeR ? 0 : 3;
    const int mbC = adjTypeC ? 0 : 3;

    // ---- hoisted sparse-mask words (LDG latency overlaps MMA phase) ----
    const int rsRow = I * 128 + (tid >> 1);
    const int rsWord = Jh * 2 + (tid & 1);
    unsigned rw0 = g_bits[mbR + 0][rsRow][rsWord];
    unsigned rw1 = g_bits[mbR + 1][rsRow][rsWord];
    unsigned rw2 = g_bits[mbR + 2][rsRow][rsWord];
    const int csCol = Jh * 64 + (tid >> 2);
    unsigned cw0 = 0, cw1 = 0, cw2 = 0;
    if (doCol) {
        cw0 = g_bits[mbC + 0][csCol][I * 4 + (tid & 3)];
        cw1 = g_bits[mbC + 1][csCol][I * 4 + (tid & 3)];
        cw2 = g_bits[mbC + 2][csCol][I * 4 + (tid & 3)];
    }

    // ldmatrix lane addressing
    const int arow = wm * 32 + (lane & 15);
    const uint32_t akb0 = (uint32_t)((lane >> 4) * 16);
    const int brow = wn * 32 + ((lane >> 4) * 8) + (lane & 7);
    const uint32_t bkb0 = (uint32_t)(((lane >> 3) & 1) * 16);
    uint32_t aRT[2], aXV[2], bRT[2], bXV[2];
#pragma unroll
    for (int mt = 0; mt < 2; mt++) {
        int r = arow + mt * 16;
        aRT[mt] = (uint32_t)(r * 128);
        aXV[mt] = (uint32_t)((r & 7) << 4);
    }
#pragma unroll
    for (int j = 0; j < 2; j++) {
        int r = brow + j * 16;
        bRT[j] = (uint32_t)(16384 + r * 128);
        bXV[j] = (uint32_t)((r & 7) << 4);
    }

    // staging decomposition: A = 1024 16B units (4/thread), B = 512 (2/thread)
    const int sRow[4] = {(tid + 0) >> 3, (tid + 256) >> 3, (tid + 512) >> 3, (tid + 768) >> 3};
    const int sSeg[4] = {(tid + 0) & 7, (tid + 256) & 7, (tid + 512) & 7, (tid + 768) & 7};
    uint32_t dA[4], dB[2];
#pragma unroll
    for (int i = 0; i < 4; i++) dA[i] = SWZ((uint32_t)(sRow[i] * 128 + sSeg[i] * 16));
#pragma unroll
    for (int i = 0; i < 2; i++)
        dB[i] = 16384u + SWZ((uint32_t)((sRow[i] & 63) * 128 + sSeg[i] * 16));

    const __half* Ap = (pass == 1) ? g_h2 : g_h1;
    const __half* Bp = (pass == 0) ? g_h1 : g_h2;
    const __half* Ag = Ap + (size_t)I * 128 * D;
    const __half* Bg = Bp + (size_t)Jh * 64 * D;
    const __half* srcA[4];
    const __half* srcB[2];
#pragma unroll
    for (int i = 0; i < 4; i++) srcA[i] = Ag + (size_t)sRow[i] * D + sSeg[i] * 8;
#pragma unroll
    for (int i = 0; i < 2; i++) srcB[i] = Bg + (size_t)(sRow[i] & 63) * D + sSeg[i] * 8;

    float cfr[8][4];
#pragma unroll
    for (int i = 0; i < 8; i++)
#pragma unroll
        for (int j = 0; j < 4; j++) cfr[i][j] = 0.0f;

    // prologue: issue chunks 0,1 -> bufs 0,1 (R13 mapping)
#pragma unroll
    for (int g = 0; g < 2; g++) {
        const uint32_t bb = sb + g * BUF_STRIDE;
#pragma unroll
        for (int i = 0; i < 4; i++) cp16(bb + dA[i], srcA[i] + g * 64);
#pragma unroll
        for (int i = 0; i < 2; i++) cp16(bb + dB[i], srcB[i] + g * 64);
        CP_COMMIT();
    }

    for (int kc = 0; kc < 8; ++kc) {
        if (kc < 7) asm volatile("cp.async.wait_group 1;" ::: "memory");
        else        asm volatile("cp.async.wait_group 0;" ::: "memory");
        __syncthreads();
        if (kc < 6) {
            const int nb = (kc + 2) % 3;
            const uint32_t bb = sb + nb * BUF_STRIDE;
#pragma unroll
            for (int i = 0; i < 4; i++) cp16(bb + dA[i], srcA[i] + (kc + 2) * 64);
#pragma unroll
            for (int i = 0; i < 2; i++) cp16(bb + dB[i], srcB[i] + (kc + 2) * 64);
            CP_COMMIT();
        }
        const uint32_t base = sb + (kc % 3) * BUF_STRIDE;
#pragma unroll
        for (int ks = 0; ks < 4; ++ks) {
            const uint32_t ko = (uint32_t)(ks * 32);
            uint32_t af[8], bf[8];
#pragma unroll
            for (int mt = 0; mt < 2; mt++)
                ldsm4(&af[mt * 4], base + aRT[mt] + ((ko + akb0) ^ aXV[mt]));
#pragma unroll
            for (int j = 0; j < 2; j++)
                ldsm4(&bf[j * 4], base + bRT[j] + ((ko + bkb0) ^ bXV[j]));
#pragma unroll
            for (int mt = 0; mt < 2; mt++)
#pragma unroll
                for (int nt = 0; nt < 4; nt++)
                    mma16816(cfr[mt * 4 + nt], &af[mt * 4], &bf[nt * 2]);
        }
    }
    // order all ldsm reads of the staging buffers before the C dump below
    __syncthreads();

    // ---- dense row epilogue (registers, mask-free) ----
#pragma unroll
    for (int g = 0; g < 4; g++) {
        const int mt = g >> 1, half = g & 1;
        const int rl = wm * 32 + mt * 16 + half * 8 + (lane >> 2);
        float s0 = 0, s1 = 0, s2 = 0;
#pragma unroll
        for (int nt = 0; nt < 4; nt++) {
#pragma unroll
            for (int e = 0; e < 2; e++) {
                float s = cfr[mt * 4 + nt][half * 2 + e];
                s0 += __expf(s * 1.25f);
                s1 += __expf(s * 1.3888889f);
                s2 += __expf(s * 1.5625f);
            }
        }
#pragma unroll
        for (int o = 1; o <= 2; o <<= 1) {
            s0 += __shfl_xor_sync(0xffffffffu, s0, o);
            s1 += __shfl_xor_sync(0xffffffffu, s1, o);
            s2 += __shfl_xor_sync(0xffffffffu, s2, o);
        }
        if ((lane & 3) == 0) {
            float* d = &sAcc[wn * 1024 + rl * 8];
            d[0] = s0; d[1] = s1; d[2] = s2;
        }
    }

    // ---- diag extraction (rare uniform branch) ----
    if (diagBlock) {
        const int off = (Jh & 1) * 64;
#pragma unroll
        for (int g = 0; g < 4; g++) {
            const int rl = wm * 32 + (g >> 1) * 16 + (g & 1) * 8 + (lane >> 2);
#pragma unroll
            for (int nt = 0; nt < 4; nt++)
#pragma unroll
                for (int e = 0; e < 2; e++) {
                    const int cl = wn * 32 + nt * 8 + (lane & 3) * 2 + e;
                    if (rl == off + cl)
                        g_acc[(38 + pass) * N + I * 128 + rl] =
                            cfr[(g >> 1) * 4 + nt][(g & 1) * 2 + e];
                }
        }
    }

    // ---- dump C fragments to smem [128][CSTRIDE] ----
#pragma unroll
    for (int mt = 0; mt < 2; mt++) {
#pragma unroll
        for (int half = 0; half < 2; half++) {
            const int row = wm * 32 + mt * 16 + half * 8 + (lane >> 2);
#pragma unroll
            for (int nt = 0; nt < 4; nt++) {
                const int col = wn * 32 + nt * 8 + (lane & 3) * 2;
                *(float2*)&Cs[row * CSTRIDE + col] =
                    make_float2(cfr[mt * 4 + nt][half * 2], cfr[mt * 4 + nt][half * 2 + 1]);
            }
        }
    }
    __syncthreads();

    // ---- sparse row-masked stats: thread (r = tid>>1, hr = tid&1) ----
    {
        const int r = tid >> 1, hr = tid & 1;
        float w0 = 0, w1 = 0, w2 = 0, w3 = 0, w4 = 0;
        unsigned hits = rw0 | rw1 | rw2;
        while (hits) {
            const int b = __ffs(hits) - 1;
            hits &= hits - 1;
            float s = Cs[r * CSTRIDE + hr * 32 + b];
            float e0 = __expf(s * 1.25f);
            float e1 = __expf(s * 1.3888889f);
            float e2 = __expf(s * 1.5625f);
            const unsigned bm = 1u << b;
            if (rw0 & bm) { w0 += e0; if (adjTypeR) w3 += e2; }
            if (rw1 & bm) { w1 += e0; if (adjTypeR) w4 += e1; }
            if (rw2 & bm) { w2 += e0; if (!adjTypeR) { w3 += e2; w4 += e1; } }
        }
        w0 += __shfl_xor_sync(0xffffffffu, w0, 1);
        w1 += __shfl_xor_sync(0xffffffffu, w1, 1);
        w2 += __shfl_xor_sync(0xffffffffu, w2, 1);
        w3 += __shfl_xor_sync(0xffffffffu, w3, 1);
        w4 += __shfl_xor_sync(0xffffffffu, w4, 1);
        if (hr == 0) {
            float* d = &sAcc[r * 8];   // bank 0, slots 3..7
            d[3] = w0; d[4] = w1; d[5] = w2; d[6] = w3; d[7] = w4;
        }
    }

    // ---- column stats (dense + sparse), only when doCol ----
    if (doCol) {
        const int c = tid >> 2, h = tid & 3;
        const int cg = Jh * 64 + c;
        float s0 = 0, s1 = 0, s2 = 0, w0 = 0, w1 = 0, w2 = 0, w3 = 0, w4 = 0;
        // dense: rows h, h+4, ..., h+124 (conflict-free LDS)
#pragma unroll 8
        for (int k = 0; k < 32; k++) {
            float s = Cs[(h + 4 * k) * CSTRIDE + c];
            s0 += __expf(s * 1.25f);
            s1 += __expf(s * 1.3888889f);
            s2 += __expf(s * 1.5625f);
        }
        // sparse masked: word q = h covers rows [32h, 32h+32)
        unsigned hits = cw0 | cw1 | cw2;
        while (hits) {
            const int b = __ffs(hits) - 1;
            hits &= hits - 1;
            float s = Cs[(h * 32 + b) * CSTRIDE + c];
            float e0 = __expf(s * 1.25f);
            float e1 = __expf(s * 1.3888889f);
            float e2 = __expf(s * 1.5625f);
            const unsigned bm = 1u << b;
            if (cw0 & bm) { w0 += e0; if (adjTypeC) w3 += e2; }
            if (cw1 & bm) { w1 += e0; if (adjTypeC) w4 += e1; }
            if (cw2 & bm) { w2 += e0; if (!adjTypeC) { w3 += e2; w4 += e1; } }
        }
#pragma unroll
        for (int o = 1; o <= 2; o <<= 1) {
            s0 += __shfl_xor_sync(0xffffffffu, s0, o);
            s1 += __shfl_xor_sync(0xffffffffu, s1, o);
            s2 += __shfl_xor_sync(0xffffffffu, s2, o);
            w0 += __shfl_xor_sync(0xffffffffu, w0, o);
            w1 += __shfl_xor_sync(0xffffffffu, w1, o);
            w2 += __shfl_xor_sync(0xffffffffu, w2, o);
            w3 += __shfl_xor_sync(0xffffffffu, w3, o);
            w4 += __shfl_xor_sync(0xffffffffu, w4, o);
        }
        if (h == 0) {
            const int sOffC[3] = {0, 6, 9};
            const int wOffC[3] = {12, 22, 27};
            atomicAdd(&g_acc[(sOffC[pass] + 0) * N + cg], s0);
            atomicAdd(&g_acc[(sOffC[pass] + 1) * N + cg], s1);
            atomicAdd(&g_acc[(sOffC[pass] + 2) * N + cg], s2);
            atomicAdd(&g_acc[(wOffC[pass] + 0) * N + cg], w0);
            atomicAdd(&g_acc[(wOffC[pass] + 1) * N + cg], w1);
            atomicAdd(&g_acc[(wOffC[pass] + 2) * N + cg], w2);
            atomicAdd(&g_acc[(wOffC[pass] + 3) * N + cg], w3);
            atomicAdd(&g_acc[(wOffC[pass] + 4) * N + cg], w4);
        }
    }
    __syncthreads();   // sAcc complete (dense banks + sparse slots)

    // ---- flush row stats: slots 0-2 sum 2 banks, slots 3-7 bank 0 only ----
    const int sOffR[3] = {0, 6, 3};
    const int wOffR[3] = {12, 22, 17};
#pragma unroll
    for (int v = 0; v < 4; v++) {
        const int slot = tid * 4 + v;
        const int row = slot >> 3, st = slot & 7;
        const float val = (st < 3) ? (sAcc[slot] + sAcc[1024 + slot]) : sAcc[slot];
        const int off = (st < 3) ? (sOffR[pass] + st) : (wOffR[pass] + st - 3);
        atomicAdd(&g_acc[off * N + I * 128 + row], val);
    }
}

// ---------------- final reduction (shuffle-based) ----------------
__global__ void final_partial_kernel() {
    const int t = threadIdx.x;  // 128
    const int lane = t & 31, w = t >> 5;
    const int i = blockIdx.x * 128 + t;
    const float invT[3] = {1.0f / 0.8f, 1.0f / 0.72f, 1.0f / 0.64f};

    const float* sI1 = g_acc + 0 * N;  const float* sX12 = g_acc + 3 * N;
    const float* sI2 = g_acc + 6 * N;  const float* sX21 = g_acc + 9 * N;
    const float* wI1 = g_acc + 12 * N; const float* wX12 = g_acc + 17 * N;
    const float* wI2 = g_acc + 22 * N; const float* wX21 = g_acc + 27 * N;
    const float* rA = g_acc + 32 * N;  const float* rG = g_acc + 35 * N;
    const float* d11 = g_acc + 38 * N; const float* d22 = g_acc + 39 * N;
    const float* d12 = g_acc + 40 * N;

    const int ktau[5] = {0, 0, 0, 2, 1};
    const int kadj1[5] = {0, 1, 2, 0, 1};
    const int kadj2[5] = {0, 1, 2, 2, 2};

    float p[13];
    {
        float e11[3], e22[3], e12[3];
#pragma unroll
        for (int tt = 0; tt < 3; tt++) {
            e11[tt] = expf(d11[i] * invT[tt]);
            e22[tt] = expf(d22[i] * invT[tt]);
            e12[tt] = expf(d12[i] * invT[tt]);
        }
#pragma unroll
        for (int k = 0; k < 5; k++) {
            int tt = ktau[k];
            float pos = e12[tt] + wI1[k * N + i] + wX12[k * N + i];
            float den = sI1[tt * N + i] + sX12[tt * N + i] - e11[tt];
            p[k] = logf(pos / den) / (2.0f * rA[kadj1[k] * N + i] + 1.0f);
        }
#pragma unroll
        for (int k = 0; k < 5; k++) {
            int tt = ktau[k];
            float pos = e12[tt] + wI2[k * N + i] + wX21[k * N + i];
            float den = sI2[tt * N + i] + sX21[tt * N + i] - e22[tt];
            p[5 + k] = logf(pos / den) / (2.0f * rG[kadj2[k] * N + i] + 1.0f);
        }
        p[10] = rA[0 * N + i]; p[11] = rA[1 * N + i]; p[12] = rA[2 * N + i];
    }

    __shared__ float part[4][13];
#pragma unroll
    for (int v = 0; v < 13; v++) {
        float x = p[v];
#pragma unroll
        for (int o = 16; o; o >>= 1) x += __shfl_xor_sync(0xffffffffu, x, o);
        if (lane == 0) part[w][v] = x;
    }
    __syncthreads();
    if (t < 13) {
        atomicAdd(&g_tot[t], part[0][t] + part[1][t] + part[2][t] + part[3][t]);
    }
}

__global__ void combine_kernel(float* __restrict__ out) {
    float L1[5], L2[5];
#pragma unroll
    for (int k = 0; k < 5; k++) {
        L1[k] = -g_tot[k] / (float)N;
        L2[k] = -g_tot[5 + k] / (float)N;
    }
    float Lc = 0.55f * L1[0] + 0.4f * L2[0];
    float Lm = 0.55f * L1[1] + 0.4f * L2[1];
    float Lf = 0.55f * L1[2] + 0.4f * L2[2];
    float Lcf = 0.55f * L1[3] + 0.4f * L2[3];
    float Lmf = 0.55f * L1[4] + 0.4f * L2[4];
    float sc = g_tot[10], sm = g_tot[11], sf = g_tot[12];
    float total = sc + sm + sf + 1e-8f;
    out[0] = (sc * Lc + sm * Lm + sf * Lf) / total + 0.2f * (Lcf + Lmf);
}

// ---------------- launch ----------------
extern "C" void kernel_launch(void* const* d_in, const int* in_sizes, int n_in,
                              void* d_out, int out_size) {
    const float* z1 = (const float*)d_in[0];
    const float* z2 = (const float*)d_in[1];

    cudaFuncSetAttribute(gram_kernel, cudaFuncAttributeMaxDynamicSharedMemorySize,
                         SMEM_BYTES);

    zero_acc_kernel<<<(ACC_TOTAL + 255) / 256, 256>>>();
    pack_adj_kernel<<<dim3(N, 6), 128>>>(
        (const float*)d_in[2], (const float*)d_in[3], (const float*)d_in[4],
        (const float*)d_in[5], (const float*)d_in[6], (const float*)d_in[7]);
    normalize_kernel<<<dim3(N, 2), 128>>>(z1, z2);
    gram_kernel<<<GRID_TILES, 256, SMEM_BYTES>>>();
    final_partial_kernel<<<32, 128>>>();
    combine_kernel<<<1, 1>>>((float*)d_out);
}